// round 14
// baseline (speedup 1.0000x reference)
#include <cuda_runtime.h>

// ---------------------------------------------------------------------------
// Decoder step: attention (B=128, L=2048, H=256) + 2x LSTM cell.
//
// attn_kernel : R10's proven version (46-47us, DRAM ~73%), UNCHANGED except
//               it also resets the LSTM dependency counter (stream-ordered,
//               safe across graph replays).
// lstm_fused  : ONE launch, grid=256, single co-resident wave:
//               blocks 0-127  : lstm1 (K=512) -> h1,c1, h1T rows of g_X2T,
//                               then signal g_bar.
//               blocks 128-255: lstm2 (K=768) -- W prologue + the 512
//                               attention-independent k (embed+hidden2)
//                               FIRST (overlapped with lstm1), brief spin on
//                               g_bar, then the 256 h1 k + epilogue.
//               Per-block: 2 h-indices (8 gate rows) x 128 batches, warps
//               split K 8-ways, thread tile 4b x 8r, X via pipelined
//               coalesced LDG.128, W via cp.async, Ws/Rs overlaid (32KB).
// ---------------------------------------------------------------------------

#define B_ 128
#define H_ 256
#define L_ 2048
#define NSPLIT 2
#define LSP (L_ / NSPLIT)           // 1024 rows per split
#define ATTN_BLOCKS (B_ * NSPLIT)   // 256 — single wave
#define M0 44.0f

__device__ float g_X1T[512 * 128];   // rows 0-255 ctx, 256-511 hidden1
__device__ float g_X2T[768 * 128];   // rows 0-255 embed, 256-511 h1, 512-767 hidden2
__device__ float g_ctx_part[ATTN_BLOCKS * H_];
__device__ float g_d[ATTN_BLOCKS];
__device__ unsigned g_cnt[B_];       // zero-init; self-resetting
__device__ unsigned g_bar;           // lstm1 completion counter (reset by attn)

// ---------------- helpers ----------------------------------------------------

__device__ __forceinline__ void online_step(
    const float4& ea, const float4& eb, const float4& ha, const float4& hb,
    float& d, float* c)
{
    float s = ea.x * ha.x + ea.y * ha.y + ea.z * ha.z + ea.w * ha.w
            + eb.x * hb.x + eb.y * hb.y + eb.z * hb.z + eb.w * hb.w;
#pragma unroll
    for (int off = 16; off; off >>= 1)
        s += __shfl_xor_sync(0xffffffffu, s, off);
    float es = __expf(s - M0);
    d += es;
    c[0] = fmaf(es, ea.x, c[0]);
    c[1] = fmaf(es, ea.y, c[1]);
    c[2] = fmaf(es, ea.z, c[2]);
    c[3] = fmaf(es, ea.w, c[3]);
    c[4] = fmaf(es, eb.x, c[4]);
    c[5] = fmaf(es, eb.y, c[5]);
    c[6] = fmaf(es, eb.z, c[6]);
    c[7] = fmaf(es, eb.w, c[7]);
}

__device__ __forceinline__ float sigmoidf_(float x) {
    return 1.f / (1.f + __expf(-x));
}

__device__ __forceinline__ void cp_async16(void* smem_dst, const void* gmem_src) {
    unsigned saddr = (unsigned)__cvta_generic_to_shared(smem_dst);
    asm volatile("cp.async.cg.shared.global [%0], [%1], 16;\n"
                 :: "r"(saddr), "l"(gmem_src));
}
__device__ __forceinline__ void cp_commit() {
    asm volatile("cp.async.commit_group;\n");
}
__device__ __forceinline__ void cp_wait0() {
    asm volatile("cp.async.wait_group 0;\n");
}

// ---------------- attention + fused combine/pack (R10, unchanged) --------------

__global__ __launch_bounds__(256, 2) void attn_kernel(
    const float* __restrict__ enc,
    const float* __restrict__ hidden1,
    const float* __restrict__ embed,
    const float* __restrict__ hidden2)
{
    const int bx   = blockIdx.x;
    const int tid  = threadIdx.x;
    const int w    = tid >> 5;
    const int lane = tid & 31;

    const int b  = bx >> 1;
    const int sp = bx & 1;

    __shared__ float h1s[H_];
    __shared__ float ctx_s[8][H_];
    __shared__ float d_s[8];
    __shared__ unsigned old_s;

    if (bx == 0 && tid == 0) g_bar = 0u;   // stream-ordered reset for lstm_fused

    h1s[tid] = hidden1[b * H_ + tid];

    // transposed static packs (tiny; overlapped with streaming)
    if (sp == 1) {
        g_X2T[tid * B_ + b]          = embed[b * H_ + tid];
        g_X2T[(512 + tid) * B_ + b]  = hidden2[b * H_ + tid];
    }
    __syncthreads();
    if (sp == 0) g_X1T[(H_ + tid) * B_ + b] = h1s[tid];

    const float4 ha = *reinterpret_cast<const float4*>(&h1s[lane * 4]);
    const float4 hb = *reinterpret_cast<const float4*>(&h1s[128 + lane * 4]);

    const float* encb = enc + (size_t)b * (L_ * H_) + (size_t)sp * (LSP * H_);

    float d[4], c[4][8];
    float4 ea[4], eb[4];
    const float* p[4];
#pragma unroll
    for (int j = 0; j < 4; j++) {
        d[j] = 0.f;
#pragma unroll
        for (int q = 0; q < 8; q++) c[j][q] = 0.f;
        p[j]  = encb + (size_t)(w + 8 * j) * H_ + lane * 4;
        ea[j] = *reinterpret_cast<const float4*>(p[j]);
        eb[j] = *reinterpret_cast<const float4*>(p[j] + 128);
    }

    const int STRIDE = 32 * H_;
    const int ITERS  = LSP / 32;          // 32
    for (int i = 0; i < ITERS - 1; i++) {
        float4 na[4], nb[4];
#pragma unroll
        for (int j = 0; j < 4; j++) {
            na[j] = *reinterpret_cast<const float4*>(p[j] + STRIDE);
            nb[j] = *reinterpret_cast<const float4*>(p[j] + STRIDE + 128);
        }
#pragma unroll
        for (int j = 0; j < 4; j++)
            online_step(ea[j], eb[j], ha, hb, d[j], c[j]);
#pragma unroll
        for (int j = 0; j < 4; j++) {
            ea[j] = na[j]; eb[j] = nb[j]; p[j] += STRIDE;
        }
    }
#pragma unroll
    for (int j = 0; j < 4; j++)
        online_step(ea[j], eb[j], ha, hb, d[j], c[j]);

    // merge 4 streams (plain sums)
#pragma unroll
    for (int j = 1; j < 4; j++) {
        d[0] += d[j];
#pragma unroll
        for (int q = 0; q < 8; q++) c[0][q] += c[j][q];
    }

    // block reduce via smem
#pragma unroll
    for (int q = 0; q < 4; q++) {
        ctx_s[w][lane * 4 + q]       = c[0][q];
        ctx_s[w][128 + lane * 4 + q] = c[0][4 + q];
    }
    if (lane == 0) d_s[w] = d[0];
    __syncthreads();

    float D = 0.f, C = 0.f;
#pragma unroll
    for (int ww = 0; ww < 8; ww++) {
        D += d_s[ww];
        C += ctx_s[ww][tid];
    }
    g_ctx_part[bx * H_ + tid] = C;
    if (tid == 0) g_d[bx] = D;

    // ---- last-arriver combine ----
    __threadfence();
    __syncthreads();
    if (tid == 0) old_s = atomicAdd(&g_cnt[b], 1u);
    __syncthreads();
    if (old_s == NSPLIT - 1) {
        __threadfence();
        float DD = 0.f, CC = 0.f;
#pragma unroll
        for (int s = 0; s < NSPLIT; s++) {
            DD += g_d[b * NSPLIT + s];
            CC += g_ctx_part[(b * NSPLIT + s) * H_ + tid];
        }
        g_X1T[tid * B_ + b] = CC / DD;
        if (tid == 0) g_cnt[b] = 0u;   // reset for next graph replay
    }
}

// ---------------- fused LSTM1 + LSTM2 -------------------------------------------

// Common GEMM micro-kernel piece: NSI stages of 8 k starting at X row kx
// (and W column kx). Updates acc[4][8].
template <int K>
__device__ __forceinline__ void gemm_span(
    const float* __restrict__ XT, const float* __restrict__ Ws,
    int kx, int nsi, int b0, float acc[4][8])
{
    float4 xv[8], xn[8];
#pragma unroll
    for (int i = 0; i < 8; i++)
        xv[i] = *reinterpret_cast<const float4*>(
            &XT[(size_t)(kx + i) * 128 + b0]);

    for (int s = 0; s < nsi; s++) {
        if (s + 1 < nsi) {
#pragma unroll
            for (int i = 0; i < 8; i++)
                xn[i] = *reinterpret_cast<const float4*>(
                    &XT[(size_t)(kx + (s + 1) * 8 + i) * 128 + b0]);
        }
#pragma unroll
        for (int i = 0; i < 8; i += 4) {
            float wr[8][4];
#pragma unroll
            for (int r = 0; r < 8; r++)
                *reinterpret_cast<float4*>(wr[r]) =
                    *reinterpret_cast<const float4*>(&Ws[r * K + kx + s * 8 + i]);
#pragma unroll
            for (int kk = 0; kk < 4; kk++) {
                float4 x = xv[i + kk];
#pragma unroll
                for (int r = 0; r < 8; r++) {
                    acc[0][r] = fmaf(x.x, wr[r][kk], acc[0][r]);
                    acc[1][r] = fmaf(x.y, wr[r][kk], acc[1][r]);
                    acc[2][r] = fmaf(x.z, wr[r][kk], acc[2][r]);
                    acc[3][r] = fmaf(x.w, wr[r][kk], acc[3][r]);
                }
            }
        }
        if (s + 1 < nsi) {
#pragma unroll
            for (int i = 0; i < 8; i++) xv[i] = xn[i];
        }
    }
}

__global__ __launch_bounds__(256, 2) void lstm_fused(
    const float* __restrict__ w_ih1, const float* __restrict__ w_hh1,
    const float* __restrict__ b_ih1, const float* __restrict__ b_hh1,
    const float* __restrict__ cell1,
    const float* __restrict__ w_ih2, const float* __restrict__ w_hh2,
    const float* __restrict__ b_ih2, const float* __restrict__ b_hh2,
    const float* __restrict__ cell2,
    float* __restrict__ out)
{
    __shared__ float S[8192];        // Ws [8][K<=768] mainloop; Rs [8][8][128] after
    float* Ws = S;
    float* Rs = S;

    const int bid  = blockIdx.x;
    const int tid  = threadIdx.x;
    const int warp = tid >> 5;
    const int lane = tid & 31;
    const int b0   = lane * 4;
    const bool l2  = (bid >= 128);
    const int h0   = (l2 ? bid - 128 : bid) * 2;

    const float* b_ih = l2 ? b_ih2 : b_ih1;
    const float* b_hh = l2 ? b_hh2 : b_hh1;
    const float* cpr  = l2 ? cell2 : cell1;

    // epilogue operand prefetch: thread = (hl = tid>>7, b = tid&127)
    const int ehl = tid >> 7;
    const int eb_ = tid & 127;
    float bias[4];
#pragma unroll
    for (int g = 0; g < 4; g++)
        bias[g] = b_ih[g * H_ + h0 + ehl] + b_hh[g * H_ + h0 + ehl];
    const float cpv = cpr[eb_ * H_ + h0 + ehl];

    float acc[4][8];
#pragma unroll
    for (int j = 0; j < 4; j++)
#pragma unroll
        for (int r = 0; r < 8; r++) acc[j][r] = 0.f;

    if (!l2) {
        // ---------------- LSTM1: K=512 (ctx 0-255 | hidden1 256-511) ----------
        constexpr int K = 512;
        // W prologue: 8 rows x 128 float4. row r -> gate r>>1, hl r&1
        for (int t = tid; t < 1024; t += 256) {
            int r = t >> 7;
            int k = (t & 127) * 4;
            int grow = (r >> 1) * H_ + h0 + (r & 1);
            const float* src = (k < 256)
                ? &w_ih1[(size_t)grow * 256 + k]
                : &w_hh1[(size_t)grow * 256 + (k - 256)];
            cp_async16(&Ws[r * K + k], src);
        }
        cp_commit();
        cp_wait0();
        __syncthreads();

        gemm_span<K>(g_X1T, Ws, warp * 64, 8, b0, acc);

        __syncthreads();
#pragma unroll
        for (int r = 0; r < 8; r++)
#pragma unroll
            for (int j = 0; j < 4; j++)
                Rs[(r * 8 + warp) * 128 + b0 + j] = acc[j][r];
        __syncthreads();

        const int h = h0 + ehl;
        float gate[4];
#pragma unroll
        for (int g = 0; g < 4; g++) {
            const int r = g * 2 + ehl;
            float s = bias[g];
#pragma unroll
            for (int w = 0; w < 8; w++)
                s += Rs[(r * 8 + w) * 128 + eb_];
            gate[g] = s;
        }
        float gi = sigmoidf_(gate[0]);
        float gf = sigmoidf_(gate[1]);
        float gg = tanhf(gate[2]);
        float go = sigmoidf_(gate[3]);
        float cn = fmaf(gf, cpv, gi * gg);
        float hn = go * tanhf(cn);

        out[65536 + eb_ * H_ + h] = cn;    // c1
        out[32768 + eb_ * H_ + h] = hn;    // h1
        g_X2T[(H_ + h) * B_ + eb_] = hn;   // h1T for lstm2

        // signal completion
        __threadfence();
        __syncthreads();
        if (tid == 0) atomicAdd(&g_bar, 1u);

    } else {
        // ---------------- LSTM2: K=768 (embed 0-255 | h1 256-511 | hid2 512-767)
        constexpr int K = 768;
        // W prologue: 8 rows x 192 float4. W col layout == X2T row layout:
        // 0-511 = w_ih2, 512-767 = w_hh2.
        for (int t = tid; t < 1536; t += 256) {
            int r = t / 192;
            int k = (t % 192) * 4;
            int grow = (r >> 1) * H_ + h0 + (r & 1);
            const float* src = (k < 512)
                ? &w_ih2[(size_t)grow * 512 + k]
                : &w_hh2[(size_t)grow * 256 + (k - 512)];
            cp_async16(&Ws[r * K + k], src);
        }
        cp_commit();
        cp_wait0();
        __syncthreads();

        // Phase A: 512 ready k (embed rows 0-255, hidden2 rows 512-767),
        // warps 0-3 -> embed span, warps 4-7 -> hidden2 span; 64 k each.
        const int kxA = (warp < 4) ? warp * 64 : 512 + (warp - 4) * 64;
        gemm_span<K>(g_X2T, Ws, kxA, 8, b0, acc);

        // wait for lstm1 (h1T rows 256-511)
        if (tid == 0) {
            while (atomicAdd(&g_bar, 0u) < 128u) __nanosleep(64);
        }
        __syncthreads();
        __threadfence();

        // Phase B: 256 h1 k, warps split 8-ways (32 k each)
        gemm_span<K>(g_X2T, Ws, 256 + warp * 32, 4, b0, acc);

        __syncthreads();
#pragma unroll
        for (int r = 0; r < 8; r++)
#pragma unroll
            for (int j = 0; j < 4; j++)
                Rs[(r * 8 + warp) * 128 + b0 + j] = acc[j][r];
        __syncthreads();

        const int h = h0 + ehl;
        float gate[4];
#pragma unroll
        for (int g = 0; g < 4; g++) {
            const int r = g * 2 + ehl;
            float s = bias[g];
#pragma unroll
            for (int w = 0; w < 8; w++)
                s += Rs[(r * 8 + w) * 128 + eb_];
            gate[g] = s;
        }
        float gi = sigmoidf_(gate[0]);
        float gf = sigmoidf_(gate[1]);
        float gg = tanhf(gate[2]);
        float go = sigmoidf_(gate[3]);
        float cn = fmaf(gf, cpv, gi * gg);
        float hn = go * tanhf(cn);

        out[131072 + eb_ * H_ + h] = cn;   // c2
        out[98304 + eb_ * H_ + h]  = hn;   // h2
        out[eb_ * H_ + h]          = hn;   // outputs
    }
}

// ---------------- launch ----------------------------------------------------------

extern "C" void kernel_launch(void* const* d_in, const int* in_sizes, int n_in,
                              void* d_out, int out_size)
{
    const float* embed   = (const float*)d_in[0];
    const float* enc     = (const float*)d_in[1];
    const float* hidden1 = (const float*)d_in[2];
    const float* cell1   = (const float*)d_in[3];
    const float* hidden2 = (const float*)d_in[4];
    const float* cell2   = (const float*)d_in[5];
    const float* w_ih1   = (const float*)d_in[6];
    const float* w_hh1   = (const float*)d_in[7];
    const float* b_ih1   = (const float*)d_in[8];
    const float* b_hh1   = (const float*)d_in[9];
    const float* w_ih2   = (const float*)d_in[10];
    const float* w_hh2   = (const float*)d_in[11];
    const float* b_ih2   = (const float*)d_in[12];
    const float* b_hh2   = (const float*)d_in[13];
    float* out = (float*)d_out;

    attn_kernel<<<ATTN_BLOCKS, 256>>>(enc, hidden1, embed, hidden2);
    lstm_fused<<<256, 256>>>(w_ih1, w_hh1, b_ih1, b_hh1, cell1,
                             w_ih2, w_hh2, b_ih2, b_hh2, cell2, out);
}